// round 4
// baseline (speedup 1.0000x reference)
#include <cuda_runtime.h>
#include <cuda_bf16.h>
#include <stdint.h>

// ---------------------------------------------------------------------------
// LennardJones: per-edge LJ energy + scatter-add of analytic forces to nodes.
// Outputs (flattened, concatenated):
//   d_out[0]              = potential_energy = 0.5 * sum_e pe_e
//   d_out[1 .. 1+3N)      = forces          = -0.5 * analytic   (exact identity)
//   d_out[1+3N .. 1+6N)   = analytic_force  = segsum(f_scalar * bv)
//
// Zero-state invariant: g_acc / g_pe are zero-initialized at module load and
// RESTORED to zero by finalize_kernel at the end of every kernel_launch call.
// This removes the separate zeroing launch entirely.
// ---------------------------------------------------------------------------

#define SCRATCH_CAP 131072  // >= n_nodes (100000); padded float4 accumulator

__device__ float4 g_acc[SCRATCH_CAP];  // per-node {fx,fy,fz,pad}, starts zeroed
__device__ double g_pe;                // sum of pe over all edges, starts zeroed

// e0 = 4*((1/3)^12 - (1/3)^6), computed in double, rounded to float
__device__ __constant__ const float E0C =
    (float)(4.0 * (1.8816764231589208e-06 - 1.3717421124828533e-03));

// ---------------------------------------------------------------------------
// 256-bit loads (sm_100+/sm_103a: LDG.E.256)

__device__ __forceinline__ void ldg256f(const float* __restrict__ p, float* v) {
    asm("ld.global.nc.v8.f32 {%0,%1,%2,%3,%4,%5,%6,%7}, [%8];"
        : "=f"(v[0]), "=f"(v[1]), "=f"(v[2]), "=f"(v[3]),
          "=f"(v[4]), "=f"(v[5]), "=f"(v[6]), "=f"(v[7])
        : "l"(p));
}

__device__ __forceinline__ void ldg256i(const int* __restrict__ p, int* v) {
    asm("ld.global.nc.v8.b32 {%0,%1,%2,%3,%4,%5,%6,%7}, [%8];"
        : "=r"(v[0]), "=r"(v[1]), "=r"(v[2]), "=r"(v[3]),
          "=r"(v[4]), "=r"(v[5]), "=r"(v[6]), "=r"(v[7])
        : "l"(p));
}

// ---------------------------------------------------------------------------
// One edge: compute pe contribution, scatter analytic force (one RED.v4).

__device__ __forceinline__ float edge_op_pad(float x, float y, float z, int n) {
    float r2  = fmaf(x, x, fmaf(y, y, z * z));
    float inv = 1.0f / r2;
    float c6  = inv * inv * inv;
    float c12 = c6 * c6;
    float fs  = -24.0f * (2.0f * c12 - c6) * inv;
    float4* p = &g_acc[n];
    asm volatile("red.global.add.v4.f32 [%0], {%1,%2,%3,%4};"
                 :: "l"(p), "f"(fs * x), "f"(fs * y), "f"(fs * z), "f"(0.0f)
                 : "memory");
    return 4.0f * (c12 - c6) - E0C;
}

__device__ __forceinline__ float edge_op_direct(float x, float y, float z, int n,
                                                float* __restrict__ acc) {
    float r2  = fmaf(x, x, fmaf(y, y, z * z));
    float inv = 1.0f / r2;
    float c6  = inv * inv * inv;
    float c12 = c6 * c6;
    float fs  = -24.0f * (2.0f * c12 - c6) * inv;
    atomicAdd(acc + 3 * n + 0, fs * x);
    atomicAdd(acc + 3 * n + 1, fs * y);
    atomicAdd(acc + 3 * n + 2, fs * z);
    return 4.0f * (c12 - c6) - E0C;
}

// ---------------------------------------------------------------------------

template <bool PAD>
__global__ void lj_main_kernel(const float* __restrict__ bv,
                               const int* __restrict__ dst,
                               float* __restrict__ acc_direct, int E) {
    int t  = blockIdx.x * blockDim.x + threadIdx.x;
    int e0 = t * 8;
    float pe = 0.0f;

    if (e0 + 7 < E) {
        // 8 edges: 3x LDG.256 coords (96B) + 1x LDG.256 dst (32B)
        float c[24];
        int   d[8];
        ldg256f(bv + 24 * t +  0, c +  0);
        ldg256f(bv + 24 * t +  8, c +  8);
        ldg256f(bv + 24 * t + 16, c + 16);
        ldg256i(dst + 8 * t, d);
        #pragma unroll
        for (int j = 0; j < 8; j++) {
            if (PAD)
                pe += edge_op_pad(c[3 * j], c[3 * j + 1], c[3 * j + 2], d[j]);
            else
                pe += edge_op_direct(c[3 * j], c[3 * j + 1], c[3 * j + 2], d[j],
                                     acc_direct);
        }
    } else {
        for (int e = e0; e < E; e++) {
            float x = bv[3 * e + 0], y = bv[3 * e + 1], z = bv[3 * e + 2];
            int n = dst[e];
            if (PAD) pe += edge_op_pad(x, y, z, n);
            else     pe += edge_op_direct(x, y, z, n, acc_direct);
        }
    }

    // block-level PE reduction -> one double atomic per block
    __shared__ float sred[8];
    unsigned lane = threadIdx.x & 31u;
    unsigned warp = threadIdx.x >> 5;
    #pragma unroll
    for (int off = 16; off > 0; off >>= 1)
        pe += __shfl_down_sync(0xFFFFFFFFu, pe, off);
    if (lane == 0) sred[warp] = pe;
    __syncthreads();
    if (warp == 0) {
        float v = (lane < (blockDim.x >> 5)) ? sred[lane] : 0.0f;
        #pragma unroll
        for (int off = 4; off > 0; off >>= 1)
            v += __shfl_down_sync(0xFFFFFFFFu, v, off);
        if (lane == 0) atomicAdd(&g_pe, (double)v);
    }
}

// ---------------------------------------------------------------------------
// Finalize: one thread per node. Reads accumulator, writes both force arrays,
// and RESTORES the zero-state invariant for the next call.

__global__ void finalize_pad_kernel(float* __restrict__ out, int N) {
    int n = blockIdx.x * blockDim.x + threadIdx.x;
    if (n < N) {
        float4 a = g_acc[n];
        g_acc[n] = make_float4(0.f, 0.f, 0.f, 0.f);  // restore invariant
        float* f  = out + 1 + 3 * n;
        float* af = out + 1 + 3 * N + 3 * n;
        f[0]  = -0.5f * a.x;  f[1]  = -0.5f * a.y;  f[2]  = -0.5f * a.z;
        af[0] = a.x;          af[1] = a.y;          af[2] = a.z;
    }
    if (n == 0) {
        out[0] = (float)(0.5 * g_pe);
        g_pe = 0.0;  // restore invariant
    }
}

// Fallback path (N > SCRATCH_CAP): accumulated directly in the analytic region.
__global__ void zero_direct_kernel(float* __restrict__ acc, int n3) {
    int i = blockIdx.x * blockDim.x + threadIdx.x;
    if (i == 0) g_pe = 0.0;
    if (i < n3) acc[i] = 0.f;
}

__global__ void finalize_direct_kernel(float* __restrict__ out, int N) {
    int i = blockIdx.x * blockDim.x + threadIdx.x;
    int total = 3 * N;
    if (i < total) {
        float a = out[1 + total + i];
        out[1 + i] = -0.5f * a;
    }
    if (i == 0) out[0] = (float)(0.5 * g_pe);
}

// ---------------------------------------------------------------------------

extern "C" void kernel_launch(void* const* d_in, const int* in_sizes, int n_in,
                              void* d_out, int out_size) {
    const float* bv  = (const float*)d_in[0];
    const int*   dst = (const int*)d_in[1];
    float* out = (float*)d_out;

    int E = in_sizes[1];
    int N = (out_size - 1) / 6;

    bool pad = (N <= SCRATCH_CAP);
    float* acc_direct = out + 1 + 3 * N;

    if (!pad) {
        int n3 = 3 * N;
        int threads = 256, blocks = (n3 + threads - 1) / threads;
        zero_direct_kernel<<<blocks, threads>>>(acc_direct, n3);
    }

    // main edge kernel: 8 edges per thread
    {
        int threads = 256;
        int nthreads_needed = (E + 7) / 8;
        int blocks = (nthreads_needed + threads - 1) / threads;
        if (pad)
            lj_main_kernel<true><<<blocks, threads>>>(bv, dst, acc_direct, E);
        else
            lj_main_kernel<false><<<blocks, threads>>>(bv, dst, acc_direct, E);
    }

    // finalize: write PE + forces, restore zero-state
    if (pad) {
        int threads = 256;
        int blocks = (N + threads - 1) / threads;
        finalize_pad_kernel<<<blocks, threads>>>(out, N);
    } else {
        int threads = 256;
        int blocks = (3 * N + threads - 1) / threads;
        finalize_direct_kernel<<<blocks, threads>>>(out, N);
    }
}